// round 6
// baseline (speedup 1.0000x reference)
#include <cuda_runtime.h>

#define DEV_INLINE __device__ __forceinline__

constexpr int NE   = 32;    // experts
constexpr int TOPK = 4;
constexpr int DH   = 1024;  // hidden
constexpr int DF   = 1024;  // intermediate
constexpr int NTOK = 1024;  // tokens (B*S)
constexpr float ALPHA = 1.702f;
constexpr float LIMIT = 7.0f;

// ---------------- static device scratch (no allocations allowed) ----------------
__device__ float g_Tn[NTOK * DH];                 // rms-normed activations, 4 MB
__device__ int   g_cnt[NE];                       // tokens per expert
__device__ int   g_tok[NE * NTOK];                // token id per (expert, slot)
__device__ float g_rw [NE * NTOK];                // routing weight per (expert, slot)
__device__ int   g_slot[NTOK * TOPK];             // token -> global slot (e*NTOK+slot)
__device__ float g_wk  [NTOK * TOPK];             // token -> routing weight
__device__ int   g_ek  [NTOK * TOPK];             // token -> expert id
__device__ float g_h [(size_t)NE * NTOK * DF];    // post-swiglu activations, 128 MB cap
__device__ float g_po[(size_t)NE * NTOK * DH];    // per-pair expert outputs, 128 MB cap

// ---------------- tf32 helpers ----------------
DEV_INLINE unsigned f2tf(float f) {
    unsigned u;
    asm("cvt.rna.tf32.f32 %0, %1;" : "=r"(u) : "f"(f));
    return u;
}

DEV_INLINE void mma8(float* c, const unsigned* a, const unsigned* b) {
    asm volatile(
        "mma.sync.aligned.m16n8k8.row.col.f32.tf32.tf32.f32 "
        "{%0,%1,%2,%3}, {%4,%5,%6,%7}, {%8,%9}, {%0,%1,%2,%3};\n"
        : "+f"(c[0]), "+f"(c[1]), "+f"(c[2]), "+f"(c[3])
        : "r"(a[0]), "r"(a[1]), "r"(a[2]), "r"(a[3]),
          "r"(b[0]), "r"(b[1]));
}

// ---------------- kernel 0: reset per-expert counters ----------------
__global__ void zero_kernel() {
    if (threadIdx.x < NE) g_cnt[threadIdx.x] = 0;
}

// ---------------- kernel 1: rmsnorm + gate + top-4 + routing tables ----------------
__global__ __launch_bounds__(256) void route_kernel(
    const float* __restrict__ x, const float* __restrict__ nsc,
    const float* __restrict__ gw, const float* __restrict__ gb)
{
    __shared__ float s_tn[DH];
    __shared__ float s_red[8];
    __shared__ float s_logit[NE];
    int t = blockIdx.x, tid = threadIdx.x;

    float4 xv = ((const float4*)(x + (size_t)t * DH))[tid];
    float ss = xv.x*xv.x + xv.y*xv.y + xv.z*xv.z + xv.w*xv.w;
    #pragma unroll
    for (int o = 16; o; o >>= 1) ss += __shfl_xor_sync(0xffffffffu, ss, o);
    if ((tid & 31) == 0) s_red[tid >> 5] = ss;
    __syncthreads();
    if (tid < 32) {
        float s = (tid < 8) ? s_red[tid] : 0.f;
        #pragma unroll
        for (int o = 4; o; o >>= 1) s += __shfl_xor_sync(0xffffffffu, s, o);
        if (tid == 0) s_red[0] = s;
    }
    __syncthreads();

    float r = rsqrtf(s_red[0] * (1.0f / DH) + 1e-5f);
    float4 nv = ((const float4*)nsc)[tid];
    float4 tn = make_float4(xv.x*r*nv.x, xv.y*r*nv.y, xv.z*r*nv.z, xv.w*r*nv.w);
    ((float4*)s_tn)[tid] = tn;
    ((float4*)(g_Tn + (size_t)t * DH))[tid] = tn;
    __syncthreads();

    int warp = tid >> 5, lane = tid & 31;
    #pragma unroll
    for (int q = 0; q < 4; q++) {
        int e = warp * 4 + q;
        const float* w = gw + (size_t)e * DH;
        float acc = 0.f;
        for (int i = lane; i < DH; i += 32) acc += s_tn[i] * w[i];
        #pragma unroll
        for (int o = 16; o; o >>= 1) acc += __shfl_xor_sync(0xffffffffu, acc, o);
        if (lane == 0) s_logit[e] = acc + gb[e];
    }
    __syncthreads();

    if (tid == 0) {
        float v[TOPK]; int id[TOPK];
        unsigned used = 0;
        #pragma unroll
        for (int k = 0; k < TOPK; k++) {
            float best = -1e30f; int bi = 0;
            for (int e = 0; e < NE; e++)
                if (!((used >> e) & 1) && s_logit[e] > best) { best = s_logit[e]; bi = e; }
            used |= 1u << bi; v[k] = best; id[k] = bi;
        }
        float m = v[0], sum = 0.f, w[TOPK];
        #pragma unroll
        for (int k = 0; k < TOPK; k++) { w[k] = __expf(v[k] - m); sum += w[k]; }
        float inv = 1.f / sum;
        #pragma unroll
        for (int k = 0; k < TOPK; k++) {
            float wk = w[k] * inv;
            int e = id[k];
            int slot = atomicAdd(&g_cnt[e], 1);
            g_tok [e * NTOK + slot] = t;
            g_rw  [e * NTOK + slot] = wk;
            g_slot[t * TOPK + k]    = e * NTOK + slot;
            g_wk  [t * TOPK + k]    = wk;
            g_ek  [t * TOPK + k]    = e;
        }
    }
}

// ---------------- grouped GEMM config ----------------
constexpr int BM = 128, BN = 128, BK = 32, PAD = 36;  // PAD keeps 16B-aligned rows + no bank conflicts

// ---------------- kernel 2: h = swiglu(gather(Tn) @ w1[e]^T + b1[e]) * route_w ----------------
__global__ __launch_bounds__(256) void mlp1_kernel(
    const float* __restrict__ w1, const float* __restrict__ b1)
{
    int e   = blockIdx.z;
    int cnt = g_cnt[e];
    int m0  = blockIdx.x * BM;
    if (m0 >= cnt) return;
    int n0  = blockIdx.y * BN;               // over 2F = 2048

    __shared__ unsigned As[BM * PAD];
    __shared__ unsigned Bs[BN * PAD];
    __shared__ int   s_tok[BM];
    __shared__ float s_rw [BM];

    int tid = threadIdx.x;
    if (tid < BM) {
        int rr = m0 + tid;
        s_tok[tid] = (rr < cnt) ? g_tok[e * NTOK + rr] : 0;
        s_rw [tid] = (rr < cnt) ? g_rw [e * NTOK + rr] : 0.f;
    }
    __syncthreads();

    int warp = tid >> 5, lane = tid & 31;
    int wm = warp & 1, wn = warp >> 1;       // 2 m-warps x 4 n-warps
    int gq = lane >> 2, qc = lane & 3;

    float acc[4][4][4];
    #pragma unroll
    for (int a = 0; a < 4; a++)
        #pragma unroll
        for (int b = 0; b < 4; b++)
            #pragma unroll
            for (int c = 0; c < 4; c++) acc[a][b][c] = 0.f;

    const float* wbase = w1 + (size_t)e * (2 * DF) * DH;

    for (int kt = 0; kt < DH / BK; kt++) {
        int k0 = kt * BK;
        #pragma unroll
        for (int rit = 0; rit < 4; rit++) {
            int idx = tid + rit * 256;
            int row = idx >> 3;
            int col = (idx & 7) << 2;
            float4 v = *(const float4*)(g_Tn + (size_t)s_tok[row] * DH + k0 + col);
            unsigned* d = &As[row * PAD + col];
            d[0] = f2tf(v.x); d[1] = f2tf(v.y); d[2] = f2tf(v.z); d[3] = f2tf(v.w);
        }
        #pragma unroll
        for (int rit = 0; rit < 4; rit++) {
            int idx = tid + rit * 256;
            int row = idx >> 3;
            int col = (idx & 7) << 2;
            float4 v = *(const float4*)(wbase + (size_t)(n0 + row) * DH + k0 + col);
            unsigned* d = &Bs[row * PAD + col];
            d[0] = f2tf(v.x); d[1] = f2tf(v.y); d[2] = f2tf(v.z); d[3] = f2tf(v.w);
        }
        __syncthreads();
        #pragma unroll
        for (int ks = 0; ks < 4; ks++) {
            int kk = ks * 8;
            unsigned a[4][4], b[4][2];
            #pragma unroll
            for (int mi = 0; mi < 4; mi++) {
                int rb = wm * 64 + mi * 16;
                a[mi][0] = As[(rb + gq    ) * PAD + kk + qc    ];
                a[mi][1] = As[(rb + gq + 8) * PAD + kk + qc    ];
                a[mi][2] = As[(rb + gq    ) * PAD + kk + qc + 4];
                a[mi][3] = As[(rb + gq + 8) * PAD + kk + qc + 4];
            }
            #pragma unroll
            for (int ni = 0; ni < 4; ni++) {
                int nb = wn * 32 + ni * 8;
                b[ni][0] = Bs[(nb + gq) * PAD + kk + qc    ];
                b[ni][1] = Bs[(nb + gq) * PAD + kk + qc + 4];
            }
            #pragma unroll
            for (int mi = 0; mi < 4; mi++)
                #pragma unroll
                for (int ni = 0; ni < 4; ni++)
                    mma8(acc[mi][ni], a[mi], b[ni]);
        }
        __syncthreads();
    }

    // epilogue: bias + clamped swiglu on interleaved column pairs, fold routing weight
    const float* bb = b1 + (size_t)e * (2 * DF);
    #pragma unroll
    for (int mi = 0; mi < 4; mi++) {
        #pragma unroll
        for (int ni = 0; ni < 4; ni++) {
            int nloc = wn * 32 + ni * 8 + 2 * qc;
            int ng   = n0 + nloc;            // even global column in [0, 2F)
            float bg = __ldg(bb + ng), bl = __ldg(bb + ng + 1);
            int f = ng >> 1;
            #pragma unroll
            for (int half = 0; half < 2; half++) {
                int mloc = wm * 64 + mi * 16 + gq + half * 8;
                int rr = m0 + mloc;
                if (rr < cnt) {
                    float gl = fminf(acc[mi][ni][2*half] + bg, LIMIT);
                    float li = fminf(fmaxf(acc[mi][ni][2*half+1] + bl, -LIMIT), LIMIT);
                    float hv = gl * (1.f / (1.f + __expf(-ALPHA * gl))) * (li + 1.f);
                    g_h[((size_t)e * NTOK + rr) * DF + f] = hv * s_rw[mloc];
                }
            }
        }
    }
}

// ---------------- kernel 3: pair_out = h @ w2[e]^T ----------------
__global__ __launch_bounds__(256) void mlp2_kernel(const float* __restrict__ w2)
{
    int e   = blockIdx.z;
    int cnt = g_cnt[e];
    int m0  = blockIdx.x * BM;
    if (m0 >= cnt) return;
    int n0  = blockIdx.y * BN;               // over H

    __shared__ unsigned As[BM * PAD];
    __shared__ unsigned Bs[BN * PAD];

    int tid = threadIdx.x;
    int warp = tid >> 5, lane = tid & 31;
    int wm = warp & 1, wn = warp >> 1;
    int gq = lane >> 2, qc = lane & 3;

    float acc[4][4][4];
    #pragma unroll
    for (int a = 0; a < 4; a++)
        #pragma unroll
        for (int b = 0; b < 4; b++)
            #pragma unroll
            for (int c = 0; c < 4; c++) acc[a][b][c] = 0.f;

    const float* wbase = w2 + (size_t)e * DH * DF;
    const float* abase = g_h + ((size_t)e * NTOK + m0) * DF;

    for (int kt = 0; kt < DF / BK; kt++) {
        int k0 = kt * BK;
        #pragma unroll
        for (int rit = 0; rit < 4; rit++) {
            int idx = tid + rit * 256;
            int row = idx >> 3;
            int col = (idx & 7) << 2;
            float4 v = *(const float4*)(abase + (size_t)row * DF + k0 + col);
            unsigned* d = &As[row * PAD + col];
            d[0] = f2tf(v.x); d[1] = f2tf(v.y); d[2] = f2tf(v.z); d[3] = f2tf(v.w);
        }
        #pragma unroll
        for (int rit = 0; rit < 4; rit++) {
            int idx = tid + rit * 256;
            int row = idx >> 3;
            int col = (idx & 7) << 2;
            float4 v = *(const float4*)(wbase + (size_t)(n0 + row) * DF + k0 + col);
            unsigned* d = &Bs[row * PAD + col];
            d[0] = f2tf(v.x); d[1] = f2tf(v.y); d[2] = f2tf(v.z); d[3] = f2tf(v.w);
        }
        __syncthreads();
        #pragma unroll
        for (int ks = 0; ks < 4; ks++) {
            int kk = ks * 8;
            unsigned a[4][4], b[4][2];
            #pragma unroll
            for (int mi = 0; mi < 4; mi++) {
                int rb = wm * 64 + mi * 16;
                a[mi][0] = As[(rb + gq    ) * PAD + kk + qc    ];
                a[mi][1] = As[(rb + gq + 8) * PAD + kk + qc    ];
                a[mi][2] = As[(rb + gq    ) * PAD + kk + qc + 4];
                a[mi][3] = As[(rb + gq + 8) * PAD + kk + qc + 4];
            }
            #pragma unroll
            for (int ni = 0; ni < 4; ni++) {
                int nb = wn * 32 + ni * 8;
                b[ni][0] = Bs[(nb + gq) * PAD + kk + qc    ];
                b[ni][1] = Bs[(nb + gq) * PAD + kk + qc + 4];
            }
            #pragma unroll
            for (int mi = 0; mi < 4; mi++)
                #pragma unroll
                for (int ni = 0; ni < 4; ni++)
                    mma8(acc[mi][ni], a[mi], b[ni]);
        }
        __syncthreads();
    }

    #pragma unroll
    for (int mi = 0; mi < 4; mi++) {
        #pragma unroll
        for (int ni = 0; ni < 4; ni++) {
            int nloc = wn * 32 + ni * 8 + 2 * qc;
            int ng   = n0 + nloc;            // even, 8B-aligned
            #pragma unroll
            for (int half = 0; half < 2; half++) {
                int mloc = wm * 64 + mi * 16 + gq + half * 8;
                int rr = m0 + mloc;
                if (rr < cnt) {
                    float2 v = make_float2(acc[mi][ni][2*half], acc[mi][ni][2*half+1]);
                    *(float2*)(g_po + ((size_t)e * NTOK + rr) * DH + ng) = v;
                }
            }
        }
    }
}

// ---------------- kernel 4: out = x + sum_k pair_out + sum_k w_k * b2[e_k] ----------------
__global__ __launch_bounds__(256) void final_kernel(
    const float* __restrict__ x, const float* __restrict__ b2, float* __restrict__ out)
{
    int t = blockIdx.x, tid = threadIdx.x;
    int i = tid * 4;
    float4 o = *(const float4*)(x + (size_t)t * DH + i);
    #pragma unroll
    for (int k = 0; k < TOPK; k++) {
        int   slot = g_slot[t * TOPK + k];
        float wk   = g_wk  [t * TOPK + k];
        int   e    = g_ek  [t * TOPK + k];
        float4 p = *(const float4*)(g_po + (size_t)slot * DH + i);
        float4 b = *(const float4*)(b2 + (size_t)e * DH + i);
        o.x += p.x + wk * b.x;
        o.y += p.y + wk * b.y;
        o.z += p.z + wk * b.z;
        o.w += p.w + wk * b.w;
    }
    *(float4*)(out + (size_t)t * DH + i) = o;
}

// ---------------- launcher ----------------
extern "C" void kernel_launch(void* const* d_in, const int* in_sizes, int n_in,
                              void* d_out, int out_size)
{
    const float* x   = (const float*)d_in[0];
    const float* nsc = (const float*)d_in[1];
    const float* gw  = (const float*)d_in[2];
    const float* gb  = (const float*)d_in[3];
    const float* w1  = (const float*)d_in[4];
    const float* b1  = (const float*)d_in[5];
    const float* w2  = (const float*)d_in[6];
    const float* b2  = (const float*)d_in[7];
    float* out = (float*)d_out;

    zero_kernel <<<1, 32>>>();
    route_kernel<<<NTOK, 256>>>(x, nsc, gw, gb);
    mlp1_kernel <<<dim3(NTOK / BM, (2 * DF) / BN, NE), 256>>>(w1, b1);
    mlp2_kernel <<<dim3(NTOK / BM, DH / BN, NE), 256>>>(w2);
    final_kernel<<<NTOK, 256>>>(x, b2, out);
}

// round 7
// speedup vs baseline: 1.4191x; 1.4191x over previous
#include <cuda_runtime.h>

#define DEV_INLINE __device__ __forceinline__

constexpr int NE   = 32;    // experts
constexpr int TOPK = 4;
constexpr int DH   = 1024;  // hidden
constexpr int DF   = 1024;  // intermediate
constexpr int NTOK = 1024;  // tokens (B*S)
constexpr float ALPHA = 1.702f;
constexpr float LIMIT = 7.0f;

// ---------------- static device scratch (no allocations allowed) ----------------
__device__ float g_Tn[NTOK * DH];                 // rms-normed activations, 4 MB
__device__ int   g_cnt[NE];                       // tokens per expert
__device__ int   g_tok[NE * NTOK];                // token id per (expert, slot)
__device__ float g_rw [NE * NTOK];                // routing weight per (expert, slot)
__device__ int   g_slot[NTOK * TOPK];             // token -> global slot (e*NTOK+slot)
__device__ float g_wk  [NTOK * TOPK];             // token -> routing weight
__device__ int   g_ek  [NTOK * TOPK];             // token -> expert id
__device__ float g_h [(size_t)NE * NTOK * DF];    // post-swiglu activations
__device__ float g_po[(size_t)NE * NTOK * DH];    // per-pair expert outputs

// ---------------- tf32 helpers ----------------
DEV_INLINE unsigned f2tf(float f) {
    unsigned u;
    asm("cvt.rna.tf32.f32 %0, %1;" : "=r"(u) : "f"(f));
    return u;
}

DEV_INLINE void mma8(float* c, const unsigned* a, const unsigned* b) {
    asm volatile(
        "mma.sync.aligned.m16n8k8.row.col.f32.tf32.tf32.f32 "
        "{%0,%1,%2,%3}, {%4,%5,%6,%7}, {%8,%9}, {%0,%1,%2,%3};\n"
        : "+f"(c[0]), "+f"(c[1]), "+f"(c[2]), "+f"(c[3])
        : "r"(a[0]), "r"(a[1]), "r"(a[2]), "r"(a[3]),
          "r"(b[0]), "r"(b[1]));
}

// ---------------- cp.async helpers ----------------
DEV_INLINE void cp16_ca(float* dst, const float* src) {
    unsigned sa = (unsigned)__cvta_generic_to_shared(dst);
    asm volatile("cp.async.ca.shared.global [%0], [%1], 16;\n" :: "r"(sa), "l"(src));
}
DEV_INLINE void cp16_cg(float* dst, const float* src) {
    unsigned sa = (unsigned)__cvta_generic_to_shared(dst);
    asm volatile("cp.async.cg.shared.global [%0], [%1], 16;\n" :: "r"(sa), "l"(src));
}
#define CP_COMMIT() asm volatile("cp.async.commit_group;\n" ::)
#define CP_WAIT1()  asm volatile("cp.async.wait_group 1;\n" ::)
#define CP_WAIT0()  asm volatile("cp.async.wait_group 0;\n" ::)

// ---------------- kernel 0: reset per-expert counters ----------------
__global__ void zero_kernel() {
    if (threadIdx.x < NE) g_cnt[threadIdx.x] = 0;
}

// ---------------- kernel 1: rmsnorm + gate + top-4 + routing tables ----------------
__global__ __launch_bounds__(256) void route_kernel(
    const float* __restrict__ x, const float* __restrict__ nsc,
    const float* __restrict__ gw, const float* __restrict__ gb)
{
    __shared__ float s_tn[DH];
    __shared__ float s_red[8];
    __shared__ float s_logit[NE];
    int t = blockIdx.x, tid = threadIdx.x;

    float4 xv = ((const float4*)(x + (size_t)t * DH))[tid];
    float ss = xv.x*xv.x + xv.y*xv.y + xv.z*xv.z + xv.w*xv.w;
    #pragma unroll
    for (int o = 16; o; o >>= 1) ss += __shfl_xor_sync(0xffffffffu, ss, o);
    if ((tid & 31) == 0) s_red[tid >> 5] = ss;
    __syncthreads();
    if (tid < 32) {
        float s = (tid < 8) ? s_red[tid] : 0.f;
        #pragma unroll
        for (int o = 4; o; o >>= 1) s += __shfl_xor_sync(0xffffffffu, s, o);
        if (tid == 0) s_red[0] = s;
    }
    __syncthreads();

    float r = rsqrtf(s_red[0] * (1.0f / DH) + 1e-5f);
    float4 nv = ((const float4*)nsc)[tid];
    float4 tn = make_float4(xv.x*r*nv.x, xv.y*r*nv.y, xv.z*r*nv.z, xv.w*r*nv.w);
    ((float4*)s_tn)[tid] = tn;
    ((float4*)(g_Tn + (size_t)t * DH))[tid] = tn;
    __syncthreads();

    int warp = tid >> 5, lane = tid & 31;
    #pragma unroll
    for (int q = 0; q < 4; q++) {
        int e = warp * 4 + q;
        const float* w = gw + (size_t)e * DH;
        float acc = 0.f;
        for (int i = lane; i < DH; i += 32) acc += s_tn[i] * w[i];
        #pragma unroll
        for (int o = 16; o; o >>= 1) acc += __shfl_xor_sync(0xffffffffu, acc, o);
        if (lane == 0) s_logit[e] = acc + gb[e];
    }
    __syncthreads();

    if (tid == 0) {
        float v[TOPK]; int id[TOPK];
        unsigned used = 0;
        #pragma unroll
        for (int k = 0; k < TOPK; k++) {
            float best = -1e30f; int bi = 0;
            for (int e = 0; e < NE; e++)
                if (!((used >> e) & 1) && s_logit[e] > best) { best = s_logit[e]; bi = e; }
            used |= 1u << bi; v[k] = best; id[k] = bi;
        }
        float m = v[0], sum = 0.f, w[TOPK];
        #pragma unroll
        for (int k = 0; k < TOPK; k++) { w[k] = __expf(v[k] - m); sum += w[k]; }
        float inv = 1.f / sum;
        #pragma unroll
        for (int k = 0; k < TOPK; k++) {
            float wk = w[k] * inv;
            int e = id[k];
            int slot = atomicAdd(&g_cnt[e], 1);
            g_tok [e * NTOK + slot] = t;
            g_rw  [e * NTOK + slot] = wk;
            g_slot[t * TOPK + k]    = e * NTOK + slot;
            g_wk  [t * TOPK + k]    = wk;
            g_ek  [t * TOPK + k]    = e;
        }
    }
}

// ---------------- grouped GEMM config ----------------
constexpr int BM = 128, BN = 128, BK = 32;
constexpr int PADK = 36;                  // pitch in floats: 144B = 9*16B (aligned + conflict-free)
constexpr int TILE_F = BM * PADK;         // 4608 floats per tile
constexpr int STG_F  = 2 * TILE_F;        // A + B per stage
constexpr int SMEM_BYTES = 2 * STG_F * 4; // 2 stages = 73728 B

// fragment compute over one BK tile held in smem (raw fp32, tf32-converted on load)
DEV_INLINE void compute_tile(const float* __restrict__ A, const float* __restrict__ B,
                             float acc[4][4][4], int wm, int wn, int gq, int qc)
{
    #pragma unroll
    for (int ks = 0; ks < 4; ks++) {
        int kk = ks * 8;
        unsigned a[4][4], b[4][2];
        #pragma unroll
        for (int mi = 0; mi < 4; mi++) {
            int rb = wm * 64 + mi * 16;
            a[mi][0] = f2tf(A[(rb + gq    ) * PADK + kk + qc    ]);
            a[mi][1] = f2tf(A[(rb + gq + 8) * PADK + kk + qc    ]);
            a[mi][2] = f2tf(A[(rb + gq    ) * PADK + kk + qc + 4]);
            a[mi][3] = f2tf(A[(rb + gq + 8) * PADK + kk + qc + 4]);
        }
        #pragma unroll
        for (int ni = 0; ni < 4; ni++) {
            int nb = wn * 32 + ni * 8;
            b[ni][0] = f2tf(B[(nb + gq) * PADK + kk + qc    ]);
            b[ni][1] = f2tf(B[(nb + gq) * PADK + kk + qc + 4]);
        }
        #pragma unroll
        for (int mi = 0; mi < 4; mi++)
            #pragma unroll
            for (int ni = 0; ni < 4; ni++)
                mma8(acc[mi][ni], a[mi], b[ni]);
    }
}

// ---------------- kernel 2: h = swiglu(gather(Tn) @ w1[e]^T + b1[e]) * route_w ----------------
__global__ __launch_bounds__(256, 2) void mlp1_kernel(
    const float* __restrict__ w1, const float* __restrict__ b1)
{
    extern __shared__ float sm[];
    int e   = blockIdx.z;
    int cnt = g_cnt[e];
    int m0  = blockIdx.x * BM;
    if (m0 >= cnt) return;
    int n0  = blockIdx.y * BN;               // over 2F = 2048

    __shared__ int   s_tok[BM];
    __shared__ float s_rw [BM];

    int tid = threadIdx.x;
    if (tid < BM) {
        int rr = m0 + tid;
        s_tok[tid] = (rr < cnt) ? g_tok[e * NTOK + rr] : 0;
        s_rw [tid] = (rr < cnt) ? g_rw [e * NTOK + rr] : 0.f;
    }
    __syncthreads();

    int warp = tid >> 5, lane = tid & 31;
    int wm = warp & 1, wn = warp >> 1;       // 2 m-warps x 4 n-warps
    int gq = lane >> 2, qc = lane & 3;

    float acc[4][4][4];
    #pragma unroll
    for (int a = 0; a < 4; a++)
        #pragma unroll
        for (int b = 0; b < 4; b++)
            #pragma unroll
            for (int c = 0; c < 4; c++) acc[a][b][c] = 0.f;

    const float* wbase = w1 + (size_t)e * (2 * DF) * DH;
    int rbase = tid >> 3;                    // thread's base row (0..31)
    int col   = (tid & 7) << 2;              // 16B chunk column

    auto prefetch = [&](int kt, int s) {
        int k0 = kt * BK;
        float* dA = sm + s * STG_F;
        float* dB = dA + TILE_F;
        #pragma unroll
        for (int r = 0; r < 4; r++) {
            int rw = rbase + 32 * r;
            cp16_ca(dA + rw * PADK + col, g_Tn + (size_t)s_tok[rw] * DH + k0 + col);
        }
        #pragma unroll
        for (int r = 0; r < 4; r++) {
            int rw = rbase + 32 * r;
            cp16_cg(dB + rw * PADK + col, wbase + (size_t)(n0 + rw) * DH + k0 + col);
        }
    };

    constexpr int NKT = DH / BK;             // 32
    prefetch(0, 0);
    CP_COMMIT();

    for (int kt = 0; kt < NKT; kt++) {
        if (kt + 1 < NKT) { prefetch(kt + 1, (kt + 1) & 1); CP_COMMIT(); CP_WAIT1(); }
        else              { CP_WAIT0(); }
        __syncthreads();
        const float* A = sm + (kt & 1) * STG_F;
        compute_tile(A, A + TILE_F, acc, wm, wn, gq, qc);
        __syncthreads();
    }

    // epilogue: bias + clamped swiglu on interleaved column pairs, fold routing weight
    const float* bb = b1 + (size_t)e * (2 * DF);
    #pragma unroll
    for (int mi = 0; mi < 4; mi++) {
        #pragma unroll
        for (int ni = 0; ni < 4; ni++) {
            int nloc = wn * 32 + ni * 8 + 2 * qc;
            int ng   = n0 + nloc;            // even global column in [0, 2F)
            float bg = __ldg(bb + ng), bl = __ldg(bb + ng + 1);
            int f = ng >> 1;
            #pragma unroll
            for (int half = 0; half < 2; half++) {
                int mloc = wm * 64 + mi * 16 + gq + half * 8;
                int rr = m0 + mloc;
                if (rr < cnt) {
                    float gl = fminf(acc[mi][ni][2*half] + bg, LIMIT);
                    float li = fminf(fmaxf(acc[mi][ni][2*half+1] + bl, -LIMIT), LIMIT);
                    float hv = gl * (1.f / (1.f + __expf(-ALPHA * gl))) * (li + 1.f);
                    g_h[((size_t)e * NTOK + rr) * DF + f] = hv * s_rw[mloc];
                }
            }
        }
    }
}

// ---------------- kernel 3: pair_out = h @ w2[e]^T ----------------
__global__ __launch_bounds__(256, 2) void mlp2_kernel(const float* __restrict__ w2)
{
    extern __shared__ float sm[];
    int e   = blockIdx.z;
    int cnt = g_cnt[e];
    int m0  = blockIdx.x * BM;
    if (m0 >= cnt) return;
    int n0  = blockIdx.y * BN;               // over H

    int tid = threadIdx.x;
    int warp = tid >> 5, lane = tid & 31;
    int wm = warp & 1, wn = warp >> 1;
    int gq = lane >> 2, qc = lane & 3;

    float acc[4][4][4];
    #pragma unroll
    for (int a = 0; a < 4; a++)
        #pragma unroll
        for (int b = 0; b < 4; b++)
            #pragma unroll
            for (int c = 0; c < 4; c++) acc[a][b][c] = 0.f;

    const float* wbase = w2 + (size_t)e * DH * DF;
    const float* abase = g_h + ((size_t)e * NTOK + m0) * DF;
    int rbase = tid >> 3;
    int col   = (tid & 7) << 2;

    auto prefetch = [&](int kt, int s) {
        int k0 = kt * BK;
        float* dA = sm + s * STG_F;
        float* dB = dA + TILE_F;
        #pragma unroll
        for (int r = 0; r < 4; r++) {
            int rw = rbase + 32 * r;
            cp16_ca(dA + rw * PADK + col, abase + (size_t)rw * DF + k0 + col);
        }
        #pragma unroll
        for (int r = 0; r < 4; r++) {
            int rw = rbase + 32 * r;
            cp16_cg(dB + rw * PADK + col, wbase + (size_t)(n0 + rw) * DF + k0 + col);
        }
    };

    constexpr int NKT = DF / BK;             // 32
    prefetch(0, 0);
    CP_COMMIT();

    for (int kt = 0; kt < NKT; kt++) {
        if (kt + 1 < NKT) { prefetch(kt + 1, (kt + 1) & 1); CP_COMMIT(); CP_WAIT1(); }
        else              { CP_WAIT0(); }
        __syncthreads();
        const float* A = sm + (kt & 1) * STG_F;
        compute_tile(A, A + TILE_F, acc, wm, wn, gq, qc);
        __syncthreads();
    }

    #pragma unroll
    for (int mi = 0; mi < 4; mi++) {
        #pragma unroll
        for (int ni = 0; ni < 4; ni++) {
            int nloc = wn * 32 + ni * 8 + 2 * qc;
            int ng   = n0 + nloc;            // even, 8B-aligned
            #pragma unroll
            for (int half = 0; half < 2; half++) {
                int mloc = wm * 64 + mi * 16 + gq + half * 8;
                int rr = m0 + mloc;
                if (rr < cnt) {
                    float2 v = make_float2(acc[mi][ni][2*half], acc[mi][ni][2*half+1]);
                    *(float2*)(g_po + ((size_t)e * NTOK + rr) * DH + ng) = v;
                }
            }
        }
    }
}

// ---------------- kernel 4: out = x + sum_k pair_out + sum_k w_k * b2[e_k] ----------------
__global__ __launch_bounds__(256) void final_kernel(
    const float* __restrict__ x, const float* __restrict__ b2, float* __restrict__ out)
{
    int t = blockIdx.x, tid = threadIdx.x;
    int i = tid * 4;
    float4 o = *(const float4*)(x + (size_t)t * DH + i);
    #pragma unroll
    for (int k = 0; k < TOPK; k++) {
        int   slot = g_slot[t * TOPK + k];
        float wk   = g_wk  [t * TOPK + k];
        int   e    = g_ek  [t * TOPK + k];
        float4 p = *(const float4*)(g_po + (size_t)slot * DH + i);
        float4 b = *(const float4*)(b2 + (size_t)e * DH + i);
        o.x += p.x + wk * b.x;
        o.y += p.y + wk * b.y;
        o.z += p.z + wk * b.z;
        o.w += p.w + wk * b.w;
    }
    *(float4*)(out + (size_t)t * DH + i) = o;
}

// ---------------- launcher ----------------
extern "C" void kernel_launch(void* const* d_in, const int* in_sizes, int n_in,
                              void* d_out, int out_size)
{
    const float* x   = (const float*)d_in[0];
    const float* nsc = (const float*)d_in[1];
    const float* gw  = (const float*)d_in[2];
    const float* gb  = (const float*)d_in[3];
    const float* w1  = (const float*)d_in[4];
    const float* b1  = (const float*)d_in[5];
    const float* w2  = (const float*)d_in[6];
    const float* b2  = (const float*)d_in[7];
    float* out = (float*)d_out;

    // allow >48KB dynamic smem (idempotent, not a stream op, capture-safe)
    cudaFuncSetAttribute(mlp1_kernel, cudaFuncAttributeMaxDynamicSharedMemorySize, SMEM_BYTES);
    cudaFuncSetAttribute(mlp2_kernel, cudaFuncAttributeMaxDynamicSharedMemorySize, SMEM_BYTES);

    zero_kernel <<<1, 32>>>();
    route_kernel<<<NTOK, 256>>>(x, nsc, gw, gb);
    mlp1_kernel <<<dim3(NTOK / BM, (2 * DF) / BN, NE), 256, SMEM_BYTES>>>(w1, b1);
    mlp2_kernel <<<dim3(NTOK / BM, DH / BN, NE), 256, SMEM_BYTES>>>(w2);
    final_kernel<<<NTOK, 256>>>(x, b2, out);
}